// round 14
// baseline (speedup 1.0000x reference)
#include <cuda_runtime.h>
#include <cuda_bf16.h>
#include <math.h>

#define N_ATOMS 10000
#define E_TILE  32
#define STR     42     // floats per edge row: 20 rad | 16 ang | 4 sp | 2 pad (rows 8B-aligned)

// Output layout (flattened tuple):
//  l=0: (10000,1,20,4)  base 0        per-atom 80
//  l=1: (10000,3,18,4)  base 800000   per-atom 216
//  l=2: (10000,5,16,4)  base 2960000  per-atom 320
//  l=3: (10000,7,14,4)  base 6160000  per-atom 392

__device__ int g_rowptr[N_ATOMS + 1];

// Boundary-scatter rowptr: coalesced read of sorted I, scatter gap entries.
// rowptr[a] = first edge index e with I[e] >= a.
__global__ __launch_bounds__(256)
void rowptr_kernel(const int* __restrict__ I, int nE) {
    const int e = blockIdx.x * blockDim.x + threadIdx.x;
    if (e >= nE) return;
    if (e == 0) {
        const int a1 = I[0];
        for (int a = 0; a <= a1; a++) g_rowptr[a] = 0;
    }
    const int a0 = I[e];
    const int a1 = (e + 1 < nE) ? I[e + 1] : N_ATOMS;
    for (int a = a0 + 1; a <= a1; a++) g_rowptr[a] = e + 1;
}

__device__ __forceinline__ unsigned long long pack2(float a, float b) {
    unsigned long long r;
    asm("mov.b64 %0, {%1, %2};" : "=l"(r) : "f"(a), "f"(b));
    return r;
}
__device__ __forceinline__ void unpack2(unsigned long long v, float& a, float& b) {
    asm("mov.b64 {%0, %1}, %2;" : "=f"(a), "=f"(b) : "l"(v));
}
__device__ __forceinline__ unsigned long long mul2(unsigned long long a, unsigned long long b) {
    unsigned long long d;
    asm("mul.rn.f32x2 %0, %1, %2;" : "=l"(d) : "l"(a), "l"(b));
    return d;
}
__device__ __forceinline__ unsigned long long fma2(unsigned long long a, unsigned long long b, unsigned long long c) {
    unsigned long long d;
    asm("fma.rn.f32x2 %0, %1, %2, %3;" : "=l"(d) : "l"(a), "l"(b), "l"(c));
    return d;
}

__global__ __launch_bounds__(128, 9)
void expand_kernel(const float* __restrict__ R,
                   const int*   __restrict__ J,
                   const int*   __restrict__ species,
                   const float* __restrict__ embed,
                   float*       __restrict__ out)
{
    __shared__ float sh[4][E_TILE * STR];

    const int warp = threadIdx.x >> 5;
    const int lane = threadIdx.x & 31;
    const int atom = blockIdx.x * 4 + warp;
    float* tile = sh[warp];

    const int s0 = g_rowptr[atom];
    const int s1 = g_rowptr[atom + 1];

    // STS swizzle: lanes L and L+16 are the only bank-colliding pair (bank stride 10,
    // 10*16 % 32 == 0). XOR bit1 of the word offset for lanes >= 16.
    // Keyed on LANE ONLY; consumer unswizzles with (e & 16), e = producing lane.
    const int swz = (lane & 16) >> 3;   // 0 or 2 (words)

    // ---- per-lane mapping: q = lane*8 + 2p; pair (q,q+1) shares m, n consecutive, n even ----
    int radOff[4], angOff[4];
    #pragma unroll
    for (int p = 0; p < 4; p++) {
        int q = lane * 8 + 2 * p;
        if (q > 250) q = 250;             // lane 31 dead slots: never stored
        int n, m;
        if (q < 20)       { n = q;                          m = 0; }
        else if (q < 74)  { int qq = q - 20;  n = qq % 18;  m = 1 + qq / 18; }
        else if (q < 154) { int qq = q - 74;  n = qq % 16;  m = 4 + qq / 16; }
        else              { int qq = q - 154; n = qq % 14;  m = 9 + qq / 14; }
        radOff[p] = n;            // even -> 8B-aligned LDS.64 (swizzle preserves this)
        angOff[p] = 20 + m;
    }

    // acc[p][c] = ( out[q][c], out[q+1][c] ) packed f32x2,  q = lane*8 + 2p
    unsigned long long acc[4][4];
    #pragma unroll
    for (int p = 0; p < 4; p++)
        #pragma unroll
        for (int c = 0; c < 4; c++) acc[p][c] = 0ULL;

    for (int base = s0; base < s1; base += E_TILE) {
        const int E = min(E_TILE, s1 - base);

        // ---- producer: one edge per lane (float2 stores at swizzled even word offsets) ----
        if (lane < E) {
            const int e = base + lane;
            const float x = R[3 * e + 0];
            const float y = R[3 * e + 1];
            const float z = R[3 * e + 2];
            const float d    = x * x + y * y + z * z;
            const float rinv = rsqrtf(d);
            const float r    = d * rinv;
            const float ux = x * rinv, uy = y * rinv, uz = z * rinv;

            float sv1, c1;
            __sincosf(0.6283185307179586f * r, &sv1, &c1);
            // cutoff: cos(pi*min(r,5)/5) == c1 for r<=5; fc=0 beyond
            const float fc = (r <= 5.0f) ? (0.5f * (c1 + 1.0f)) : 0.0f;

            float* row = tile + lane * STR;
            #define ST2(w, v0, v1) *reinterpret_cast<float2*>(row + ((w) ^ swz)) = make_float2((v0), (v1))

            // radial sin(k*theta)*fc, k=1..20, dual odd/even Chebyshev chains
            const float t2 = 2.0f * (2.0f * c1 * c1 - 1.0f);   // 2*cos(2theta)
            float so_m2 = -sv1, so_m1 = sv1;                   // s_{-1}, s_1
            float se_m2 = 0.0f, se_m1 = 2.0f * c1 * sv1;       // s_0,  s_2
            ST2(0, sv1 * fc, se_m1 * fc);
            #pragma unroll
            for (int k = 3; k <= 19; k += 2) {
                const float so = t2 * so_m1 - so_m2;
                const float se = t2 * se_m1 - se_m2;
                so_m2 = so_m1; so_m1 = so;
                se_m2 = se_m1; se_m1 = se;
                ST2(k - 1, so * fc, se * fc);
            }

            // angular (real SH, reference order)
            const float x2 = ux * ux, y2 = uy * uy, z2 = uz * uz;
            ST2(20, 0.28209479177387814f,               0.4886025119029199f * uy);
            ST2(22, 0.4886025119029199f * uz,           0.4886025119029199f * ux);
            ST2(24, 1.0925484305920792f * ux * uy,      1.0925484305920792f * uy * uz);
            ST2(26, 0.31539156525252005f * (3.0f * z2 - 1.0f), 1.0925484305920792f * ux * uz);
            ST2(28, 0.5462742152960396f * (x2 - y2),    0.5900435899266435f * uy * (3.0f * x2 - y2));
            ST2(30, 2.890611442640554f * ux * uy * uz,  0.4570457994644658f * uy * (5.0f * z2 - 1.0f));
            ST2(32, 0.3731763325901154f * uz * (5.0f * z2 - 3.0f), 0.4570457994644658f * ux * (5.0f * z2 - 1.0f));
            ST2(34, 1.445305721320277f  * uz * (x2 - y2), 0.5900435899266435f * ux * (x2 - 3.0f * y2));

            const int sp = species[J[e]];
            const float4 sv = *reinterpret_cast<const float4*>(embed + 4 * sp);
            ST2(36, sv.x, sv.y);
            ST2(38, sv.z, sv.w);
            #undef ST2
        }
        __syncwarp();

        // ---- consumer: whole warp sweeps edges (addresses uniform per iteration) ----
        #pragma unroll 2
        for (int e = 0; e < E; e++) {
            const float* row = tile + e * STR;
            const int es = (e & 16) >> 3;    // producer of this row was lane e -> same swizzle key
            // species: two 8B broadcast loads
            const float2 spA = *reinterpret_cast<const float2*>(row + (36 ^ es));
            const float2 spB = *reinterpret_cast<const float2*>(row + (38 ^ es));
            const unsigned long long s0p = pack2(spA.x, spA.x);
            const unsigned long long s1p = pack2(spA.y, spA.y);
            const unsigned long long s2p = pack2(spB.x, spB.x);
            const unsigned long long s3p = pack2(spB.y, spB.y);
            #pragma unroll
            for (int p = 0; p < 4; p++) {
                const float a = row[angOff[p] ^ es];                                        // LDS.32
                const unsigned long long r01 =
                    *reinterpret_cast<const unsigned long long*>(row + (radOff[p] ^ es));   // LDS.64
                const unsigned long long p01 = mul2(r01, pack2(a, a));
                acc[p][0] = fma2(p01, s0p, acc[p][0]);
                acc[p][1] = fma2(p01, s1p, acc[p][1]);
                acc[p][2] = fma2(p01, s2p, acc[p][2]);
                acc[p][3] = fma2(p01, s3p, acc[p][3]);
            }
        }
        __syncwarp();
    }

    // ---- epilogue: unpack pair accumulators, two float4 stores per owned pair ----
    #pragma unroll
    for (int p = 0; p < 4; p++) {
        const int q = lane * 8 + 2 * p;
        if (q >= 252) break;
        float e0x, e1x, e0y, e1y, e0z, e1z, e0w, e1w;
        unpack2(acc[p][0], e0x, e1x);
        unpack2(acc[p][1], e0y, e1y);
        unpack2(acc[p][2], e0z, e1z);
        unpack2(acc[p][3], e0w, e1w);
        int off;
        if (q < 20)       off = atom * 80  + q * 4;
        else if (q < 74)  off = 800000  + atom * 216 + (q - 20)  * 4;
        else if (q < 154) off = 2960000 + atom * 320 + (q - 74)  * 4;
        else              off = 6160000 + atom * 392 + (q - 154) * 4;
        float4 o0; o0.x = e0x; o0.y = e0y; o0.z = e0z; o0.w = e0w;
        float4 o1; o1.x = e1x; o1.y = e1y; o1.z = e1z; o1.w = e1w;
        *reinterpret_cast<float4*>(out + off)     = o0;
        *reinterpret_cast<float4*>(out + off + 4) = o1;
    }
}

extern "C" void kernel_launch(void* const* d_in, const int* in_sizes, int n_in,
                              void* d_out, int out_size)
{
    const float* R       = (const float*)d_in[0];
    const int*   I       = (const int*)  d_in[1];
    const int*   J       = (const int*)  d_in[2];
    const int*   species = (const int*)  d_in[3];
    const float* embed   = (const float*)d_in[4];
    float* out = (float*)d_out;
    const int nE = in_sizes[1];

    rowptr_kernel<<<(nE + 255) / 256, 256>>>(I, nE);
    expand_kernel<<<N_ATOMS / 4, 128>>>(R, J, species, embed, out);
}

// round 15
// speedup vs baseline: 1.2018x; 1.2018x over previous
#include <cuda_runtime.h>
#include <cuda_bf16.h>
#include <math.h>

#define N_ATOMS 10000
#define MAX_EDGES 200000
#define E_TILE  32
#define STR     42     // floats per edge row: 20 rad | 16 ang | 4 sp | 2 pad (rows 8B-aligned)

// Output layout (flattened tuple):
//  l=0: (10000,1,20,4)  base 0        per-atom 80
//  l=1: (10000,3,18,4)  base 800000   per-atom 216
//  l=2: (10000,5,16,4)  base 2960000  per-atom 320
//  l=3: (10000,7,14,4)  base 6160000  per-atom 392

__device__ int g_rowptr[N_ATOMS + 1];
__device__ __align__(16) float g_spE[MAX_EDGES * 4];   // pre-gathered species embedding per edge (3.2MB)

// Fused prep kernel: boundary-scatter rowptr + per-edge species-embedding gather.
// rowptr[a] = first edge index e with I[e] >= a.
__global__ __launch_bounds__(256)
void prep_kernel(const int* __restrict__ I,
                 const int* __restrict__ J,
                 const int* __restrict__ species,
                 const float* __restrict__ embed,
                 int nE) {
    const int e = blockIdx.x * blockDim.x + threadIdx.x;
    if (e >= nE) return;
    // species-embedding pre-gather (dependent chain hidden across 200K threads)
    const int sp = species[J[e]];
    *reinterpret_cast<float4*>(g_spE + 4 * e) =
        *reinterpret_cast<const float4*>(embed + 4 * sp);
    // rowptr boundary scatter
    if (e == 0) {
        const int a1 = I[0];
        for (int a = 0; a <= a1; a++) g_rowptr[a] = 0;
    }
    const int a0 = I[e];
    const int a1 = (e + 1 < nE) ? I[e + 1] : N_ATOMS;
    for (int a = a0 + 1; a <= a1; a++) g_rowptr[a] = e + 1;
}

__device__ __forceinline__ unsigned long long pack2(float a, float b) {
    unsigned long long r;
    asm("mov.b64 %0, {%1, %2};" : "=l"(r) : "f"(a), "f"(b));
    return r;
}
__device__ __forceinline__ void unpack2(unsigned long long v, float& a, float& b) {
    asm("mov.b64 {%0, %1}, %2;" : "=f"(a), "=f"(b) : "l"(v));
}
__device__ __forceinline__ unsigned long long mul2(unsigned long long a, unsigned long long b) {
    unsigned long long d;
    asm("mul.rn.f32x2 %0, %1, %2;" : "=l"(d) : "l"(a), "l"(b));
    return d;
}
__device__ __forceinline__ unsigned long long fma2(unsigned long long a, unsigned long long b, unsigned long long c) {
    unsigned long long d;
    asm("fma.rn.f32x2 %0, %1, %2, %3;" : "=l"(d) : "l"(a), "l"(b), "l"(c));
    return d;
}

__global__ __launch_bounds__(128, 8)
void expand_kernel(const float* __restrict__ R,
                   float*       __restrict__ out)
{
    __shared__ float sh[4][E_TILE * STR];

    const int warp = threadIdx.x >> 5;
    const int lane = threadIdx.x & 31;
    const int atom = blockIdx.x * 4 + warp;
    float* tile = sh[warp];

    const int s0 = g_rowptr[atom];
    const int s1 = g_rowptr[atom + 1];

    // STS swizzle: lanes L and L+16 are the only bank-colliding pair (bank stride 10,
    // 10*16 % 32 == 0). XOR bit1 of the word offset for lanes >= 16.
    // Keyed on LANE ONLY; consumer unswizzles with (e & 16), e = producing lane.
    const int swz = (lane & 16) >> 3;   // 0 or 2 (words)

    // ---- per-lane mapping: q = lane*8 + 2p; pair (q,q+1) shares m, n consecutive, n even ----
    int radOff[4], angOff[4];
    #pragma unroll
    for (int p = 0; p < 4; p++) {
        int q = lane * 8 + 2 * p;
        if (q > 250) q = 250;             // lane 31 dead slots: never stored
        int n, m;
        if (q < 20)       { n = q;                          m = 0; }
        else if (q < 74)  { int qq = q - 20;  n = qq % 18;  m = 1 + qq / 18; }
        else if (q < 154) { int qq = q - 74;  n = qq % 16;  m = 4 + qq / 16; }
        else              { int qq = q - 154; n = qq % 14;  m = 9 + qq / 14; }
        radOff[p] = n;            // even -> 8B-aligned LDS.64 (swizzle preserves this)
        angOff[p] = 20 + m;
    }

    // acc[p][c] = ( out[q][c], out[q+1][c] ) packed f32x2,  q = lane*8 + 2p
    unsigned long long acc[4][4];
    #pragma unroll
    for (int p = 0; p < 4; p++)
        #pragma unroll
        for (int c = 0; c < 4; c++) acc[p][c] = 0ULL;

    for (int base = s0; base < s1; base += E_TILE) {
        const int E = min(E_TILE, s1 - base);

        // ---- producer: one edge per lane (all loads independent; no dependent chains) ----
        if (lane < E) {
            const int e = base + lane;
            const float4 sv = *reinterpret_cast<const float4*>(g_spE + 4 * e);   // pre-gathered
            const float x = R[3 * e + 0];
            const float y = R[3 * e + 1];
            const float z = R[3 * e + 2];
            const float d    = x * x + y * y + z * z;
            const float rinv = rsqrtf(d);
            const float r    = d * rinv;
            const float ux = x * rinv, uy = y * rinv, uz = z * rinv;

            float sv1, c1;
            __sincosf(0.6283185307179586f * r, &sv1, &c1);
            // cutoff: cos(pi*min(r,5)/5) == c1 for r<=5; fc=0 beyond
            const float fc = (r <= 5.0f) ? (0.5f * (c1 + 1.0f)) : 0.0f;

            float* row = tile + lane * STR;
            #define ST2(w, v0, v1) *reinterpret_cast<float2*>(row + ((w) ^ swz)) = make_float2((v0), (v1))

            // radial sin(k*theta)*fc, k=1..20, dual odd/even Chebyshev chains
            const float t2 = 2.0f * (2.0f * c1 * c1 - 1.0f);   // 2*cos(2theta)
            float so_m2 = -sv1, so_m1 = sv1;                   // s_{-1}, s_1
            float se_m2 = 0.0f, se_m1 = 2.0f * c1 * sv1;       // s_0,  s_2
            ST2(0, sv1 * fc, se_m1 * fc);
            #pragma unroll
            for (int k = 3; k <= 19; k += 2) {
                const float so = t2 * so_m1 - so_m2;
                const float se = t2 * se_m1 - se_m2;
                so_m2 = so_m1; so_m1 = so;
                se_m2 = se_m1; se_m1 = se;
                ST2(k - 1, so * fc, se * fc);
            }

            // angular (real SH, reference order)
            const float x2 = ux * ux, y2 = uy * uy, z2 = uz * uz;
            ST2(20, 0.28209479177387814f,               0.4886025119029199f * uy);
            ST2(22, 0.4886025119029199f * uz,           0.4886025119029199f * ux);
            ST2(24, 1.0925484305920792f * ux * uy,      1.0925484305920792f * uy * uz);
            ST2(26, 0.31539156525252005f * (3.0f * z2 - 1.0f), 1.0925484305920792f * ux * uz);
            ST2(28, 0.5462742152960396f * (x2 - y2),    0.5900435899266435f * uy * (3.0f * x2 - y2));
            ST2(30, 2.890611442640554f * ux * uy * uz,  0.4570457994644658f * uy * (5.0f * z2 - 1.0f));
            ST2(32, 0.3731763325901154f * uz * (5.0f * z2 - 3.0f), 0.4570457994644658f * ux * (5.0f * z2 - 1.0f));
            ST2(34, 1.445305721320277f  * uz * (x2 - y2), 0.5900435899266435f * ux * (x2 - 3.0f * y2));

            ST2(36, sv.x, sv.y);
            ST2(38, sv.z, sv.w);
            #undef ST2
        }
        __syncwarp();

        // ---- consumer: whole warp sweeps edges (addresses uniform per iteration) ----
        #pragma unroll 2
        for (int e = 0; e < E; e++) {
            const float* row = tile + e * STR;
            const int es = (e & 16) >> 3;    // producer of this row was lane e -> same swizzle key
            // species: two 8B broadcast loads
            const float2 spA = *reinterpret_cast<const float2*>(row + (36 ^ es));
            const float2 spB = *reinterpret_cast<const float2*>(row + (38 ^ es));
            const unsigned long long s0p = pack2(spA.x, spA.x);
            const unsigned long long s1p = pack2(spA.y, spA.y);
            const unsigned long long s2p = pack2(spB.x, spB.x);
            const unsigned long long s3p = pack2(spB.y, spB.y);
            #pragma unroll
            for (int p = 0; p < 4; p++) {
                const float a = row[angOff[p] ^ es];                                        // LDS.32
                const unsigned long long r01 =
                    *reinterpret_cast<const unsigned long long*>(row + (radOff[p] ^ es));   // LDS.64
                const unsigned long long p01 = mul2(r01, pack2(a, a));
                acc[p][0] = fma2(p01, s0p, acc[p][0]);
                acc[p][1] = fma2(p01, s1p, acc[p][1]);
                acc[p][2] = fma2(p01, s2p, acc[p][2]);
                acc[p][3] = fma2(p01, s3p, acc[p][3]);
            }
        }
        __syncwarp();
    }

    // ---- epilogue: unpack pair accumulators, two float4 stores per owned pair ----
    #pragma unroll
    for (int p = 0; p < 4; p++) {
        const int q = lane * 8 + 2 * p;
        if (q >= 252) break;
        float e0x, e1x, e0y, e1y, e0z, e1z, e0w, e1w;
        unpack2(acc[p][0], e0x, e1x);
        unpack2(acc[p][1], e0y, e1y);
        unpack2(acc[p][2], e0z, e1z);
        unpack2(acc[p][3], e0w, e1w);
        int off;
        if (q < 20)       off = atom * 80  + q * 4;
        else if (q < 74)  off = 800000  + atom * 216 + (q - 20)  * 4;
        else if (q < 154) off = 2960000 + atom * 320 + (q - 74)  * 4;
        else              off = 6160000 + atom * 392 + (q - 154) * 4;
        float4 o0; o0.x = e0x; o0.y = e0y; o0.z = e0z; o0.w = e0w;
        float4 o1; o1.x = e1x; o1.y = e1y; o1.z = e1z; o1.w = e1w;
        *reinterpret_cast<float4*>(out + off)     = o0;
        *reinterpret_cast<float4*>(out + off + 4) = o1;
    }
}

extern "C" void kernel_launch(void* const* d_in, const int* in_sizes, int n_in,
                              void* d_out, int out_size)
{
    const float* R       = (const float*)d_in[0];
    const int*   I       = (const int*)  d_in[1];
    const int*   J       = (const int*)  d_in[2];
    const int*   species = (const int*)  d_in[3];
    const float* embed   = (const float*)d_in[4];
    float* out = (float*)d_out;
    const int nE = in_sizes[1];

    prep_kernel<<<(nE + 255) / 256, 256>>>(I, J, species, embed, nE);
    expand_kernel<<<N_ATOMS / 4, 128>>>(R, out);
}

// round 16
// speedup vs baseline: 1.2492x; 1.0395x over previous
#include <cuda_runtime.h>
#include <cuda_bf16.h>
#include <math.h>

#define N_ATOMS 10000
#define MAX_EDGES 200000
#define E_TILE  32
#define STR     42     // floats per edge row: 20 rad | 16 ang | 4 sp | 2 pad (rows 8B-aligned)

// Output layout (flattened tuple):
//  l=0: (10000,1,20,4)  base 0        per-atom 80
//  l=1: (10000,3,18,4)  base 800000   per-atom 216
//  l=2: (10000,5,16,4)  base 2960000  per-atom 320
//  l=3: (10000,7,14,4)  base 6160000  per-atom 392

__device__ int g_rowptr[N_ATOMS + 1];
__device__ __align__(16) float g_spE[MAX_EDGES * 4];   // pre-gathered species embedding per edge (3.2MB)

// Fused prep kernel: boundary-scatter rowptr + per-edge species-embedding gather.
// rowptr[a] = first edge index e with I[e] >= a.
__global__ __launch_bounds__(256)
void prep_kernel(const int* __restrict__ I,
                 const int* __restrict__ J,
                 const int* __restrict__ species,
                 const float* __restrict__ embed,
                 int nE) {
    const int e = blockIdx.x * blockDim.x + threadIdx.x;
    if (e >= nE) return;
    // species-embedding pre-gather (dependent chain hidden across 200K threads)
    const int sp = species[J[e]];
    *reinterpret_cast<float4*>(g_spE + 4 * e) =
        *reinterpret_cast<const float4*>(embed + 4 * sp);
    // rowptr boundary scatter
    if (e == 0) {
        const int a1 = I[0];
        for (int a = 0; a <= a1; a++) g_rowptr[a] = 0;
    }
    const int a0 = I[e];
    const int a1 = (e + 1 < nE) ? I[e + 1] : N_ATOMS;
    for (int a = a0 + 1; a <= a1; a++) g_rowptr[a] = e + 1;
}

__device__ __forceinline__ unsigned long long pack2(float a, float b) {
    unsigned long long r;
    asm("mov.b64 %0, {%1, %2};" : "=l"(r) : "f"(a), "f"(b));
    return r;
}
__device__ __forceinline__ void unpack2(unsigned long long v, float& a, float& b) {
    asm("mov.b64 {%0, %1}, %2;" : "=f"(a), "=f"(b) : "l"(v));
}
__device__ __forceinline__ unsigned long long mul2(unsigned long long a, unsigned long long b) {
    unsigned long long d;
    asm("mul.rn.f32x2 %0, %1, %2;" : "=l"(d) : "l"(a), "l"(b));
    return d;
}
__device__ __forceinline__ unsigned long long fma2(unsigned long long a, unsigned long long b, unsigned long long c) {
    unsigned long long d;
    asm("fma.rn.f32x2 %0, %1, %2, %3;" : "=l"(d) : "l"(a), "l"(b), "l"(c));
    return d;
}

// One warp per CTA, one atom per CTA: HW scheduler backfills at warp granularity,
// eliminating the max-of-4-warps CTA retire penalty.
__global__ __launch_bounds__(32)
void expand_kernel(const float* __restrict__ R,
                   float*       __restrict__ out)
{
    __shared__ float tile[E_TILE * STR];

    const int lane = threadIdx.x & 31;
    const int atom = blockIdx.x;

    const int s0 = g_rowptr[atom];
    const int s1 = g_rowptr[atom + 1];

    // STS swizzle: lanes L and L+16 are the only bank-colliding pair (bank stride 10,
    // 10*16 % 32 == 0). XOR bit1 of the word offset for lanes >= 16.
    // Keyed on LANE ONLY; consumer unswizzles with (e & 16), e = producing lane.
    const int swz = (lane & 16) >> 3;   // 0 or 2 (words)

    // ---- per-lane mapping: q = lane*8 + 2p; pair (q,q+1) shares m, n consecutive, n even ----
    int radOff[4], angOff[4];
    #pragma unroll
    for (int p = 0; p < 4; p++) {
        int q = lane * 8 + 2 * p;
        if (q > 250) q = 250;             // lane 31 dead slots: never stored
        int n, m;
        if (q < 20)       { n = q;                          m = 0; }
        else if (q < 74)  { int qq = q - 20;  n = qq % 18;  m = 1 + qq / 18; }
        else if (q < 154) { int qq = q - 74;  n = qq % 16;  m = 4 + qq / 16; }
        else              { int qq = q - 154; n = qq % 14;  m = 9 + qq / 14; }
        radOff[p] = n;            // even -> 8B-aligned LDS.64 (swizzle preserves this)
        angOff[p] = 20 + m;
    }

    // acc[p][c] = ( out[q][c], out[q+1][c] ) packed f32x2,  q = lane*8 + 2p
    unsigned long long acc[4][4];
    #pragma unroll
    for (int p = 0; p < 4; p++)
        #pragma unroll
        for (int c = 0; c < 4; c++) acc[p][c] = 0ULL;

    for (int base = s0; base < s1; base += E_TILE) {
        const int E = min(E_TILE, s1 - base);

        // ---- producer: one edge per lane (all loads independent; no dependent chains) ----
        if (lane < E) {
            const int e = base + lane;
            const float4 sv = *reinterpret_cast<const float4*>(g_spE + 4 * e);   // pre-gathered
            const float x = R[3 * e + 0];
            const float y = R[3 * e + 1];
            const float z = R[3 * e + 2];
            const float d    = x * x + y * y + z * z;
            const float rinv = rsqrtf(d);
            const float r    = d * rinv;
            const float ux = x * rinv, uy = y * rinv, uz = z * rinv;

            float sv1, c1;
            __sincosf(0.6283185307179586f * r, &sv1, &c1);
            // cutoff: cos(pi*min(r,5)/5) == c1 for r<=5; fc=0 beyond
            const float fc = (r <= 5.0f) ? (0.5f * (c1 + 1.0f)) : 0.0f;

            float* row = tile + lane * STR;
            #define ST2(w, v0, v1) *reinterpret_cast<float2*>(row + ((w) ^ swz)) = make_float2((v0), (v1))

            // radial sin(k*theta)*fc, k=1..20, dual odd/even Chebyshev chains
            const float t2 = 2.0f * (2.0f * c1 * c1 - 1.0f);   // 2*cos(2theta)
            float so_m2 = -sv1, so_m1 = sv1;                   // s_{-1}, s_1
            float se_m2 = 0.0f, se_m1 = 2.0f * c1 * sv1;       // s_0,  s_2
            ST2(0, sv1 * fc, se_m1 * fc);
            #pragma unroll
            for (int k = 3; k <= 19; k += 2) {
                const float so = t2 * so_m1 - so_m2;
                const float se = t2 * se_m1 - se_m2;
                so_m2 = so_m1; so_m1 = so;
                se_m2 = se_m1; se_m1 = se;
                ST2(k - 1, so * fc, se * fc);
            }

            // angular (real SH, reference order)
            const float x2 = ux * ux, y2 = uy * uy, z2 = uz * uz;
            ST2(20, 0.28209479177387814f,               0.4886025119029199f * uy);
            ST2(22, 0.4886025119029199f * uz,           0.4886025119029199f * ux);
            ST2(24, 1.0925484305920792f * ux * uy,      1.0925484305920792f * uy * uz);
            ST2(26, 0.31539156525252005f * (3.0f * z2 - 1.0f), 1.0925484305920792f * ux * uz);
            ST2(28, 0.5462742152960396f * (x2 - y2),    0.5900435899266435f * uy * (3.0f * x2 - y2));
            ST2(30, 2.890611442640554f * ux * uy * uz,  0.4570457994644658f * uy * (5.0f * z2 - 1.0f));
            ST2(32, 0.3731763325901154f * uz * (5.0f * z2 - 3.0f), 0.4570457994644658f * ux * (5.0f * z2 - 1.0f));
            ST2(34, 1.445305721320277f  * uz * (x2 - y2), 0.5900435899266435f * ux * (x2 - 3.0f * y2));

            ST2(36, sv.x, sv.y);
            ST2(38, sv.z, sv.w);
            #undef ST2
        }
        __syncwarp();

        // ---- consumer: whole warp sweeps edges (addresses uniform per iteration) ----
        #pragma unroll 2
        for (int e = 0; e < E; e++) {
            const float* row = tile + e * STR;
            const int es = (e & 16) >> 3;    // producer of this row was lane e -> same swizzle key
            // species: two 8B broadcast loads
            const float2 spA = *reinterpret_cast<const float2*>(row + (36 ^ es));
            const float2 spB = *reinterpret_cast<const float2*>(row + (38 ^ es));
            const unsigned long long s0p = pack2(spA.x, spA.x);
            const unsigned long long s1p = pack2(spA.y, spA.y);
            const unsigned long long s2p = pack2(spB.x, spB.x);
            const unsigned long long s3p = pack2(spB.y, spB.y);
            #pragma unroll
            for (int p = 0; p < 4; p++) {
                const float a = row[angOff[p] ^ es];                                        // LDS.32
                const unsigned long long r01 =
                    *reinterpret_cast<const unsigned long long*>(row + (radOff[p] ^ es));   // LDS.64
                const unsigned long long p01 = mul2(r01, pack2(a, a));
                acc[p][0] = fma2(p01, s0p, acc[p][0]);
                acc[p][1] = fma2(p01, s1p, acc[p][1]);
                acc[p][2] = fma2(p01, s2p, acc[p][2]);
                acc[p][3] = fma2(p01, s3p, acc[p][3]);
            }
        }
        __syncwarp();
    }

    // ---- epilogue: unpack pair accumulators, two float4 stores per owned pair ----
    #pragma unroll
    for (int p = 0; p < 4; p++) {
        const int q = lane * 8 + 2 * p;
        if (q >= 252) break;
        float e0x, e1x, e0y, e1y, e0z, e1z, e0w, e1w;
        unpack2(acc[p][0], e0x, e1x);
        unpack2(acc[p][1], e0y, e1y);
        unpack2(acc[p][2], e0z, e1z);
        unpack2(acc[p][3], e0w, e1w);
        int off;
        if (q < 20)       off = atom * 80  + q * 4;
        else if (q < 74)  off = 800000  + atom * 216 + (q - 20)  * 4;
        else if (q < 154) off = 2960000 + atom * 320 + (q - 74)  * 4;
        else              off = 6160000 + atom * 392 + (q - 154) * 4;
        float4 o0; o0.x = e0x; o0.y = e0y; o0.z = e0z; o0.w = e0w;
        float4 o1; o1.x = e1x; o1.y = e1y; o1.z = e1z; o1.w = e1w;
        *reinterpret_cast<float4*>(out + off)     = o0;
        *reinterpret_cast<float4*>(out + off + 4) = o1;
    }
}

extern "C" void kernel_launch(void* const* d_in, const int* in_sizes, int n_in,
                              void* d_out, int out_size)
{
    const float* R       = (const float*)d_in[0];
    const int*   I       = (const int*)  d_in[1];
    const int*   J       = (const int*)  d_in[2];
    const int*   species = (const int*)  d_in[3];
    const float* embed   = (const float*)d_in[4];
    float* out = (float*)d_out;
    const int nE = in_sizes[1];

    prep_kernel<<<(nE + 255) / 256, 256>>>(I, J, species, embed, nE);
    expand_kernel<<<N_ATOMS, 32>>>(R, out);
}